// round 17
// baseline (speedup 1.0000x reference)
#include <cuda_runtime.h>
#include <cuda_fp16.h>
#include <math.h>
#include <stdint.h>

#define NSEQ   1024
#define NBATCH 8
#define NDIM   512
#define NHEADS 8
#define NDH    64
#define NHD    512
#define NFF    2048
#define MROWS  (NBATCH*NSEQ)
#define ATT_ELEMS ((size_t)NBATCH*NHEADS*NSEQ*NSEQ)
#define X_ELEMS   ((size_t)MROWS*NDIM)

// transposed weight offsets (elements, within one layer's block)
#define WQKVT 0
#define WKRT  786432
#define WOUTT 1048576
#define W1T   1310720
#define W2T   2359296
#define WT_TOTAL 3407872

// ---------------- scratch --------------------------------------------------
static __device__ float g_x [MROWS*NDIM];
static __device__ float g_bk[NBATCH*NHEADS*NSEQ];
static __device__ float g_br[NBATCH*NHEADS*NSEQ];
static __device__ __half g_ac[NBATCH*NHEADS*NSEQ*NSEQ];
static __device__ __half g_bd[NBATCH*NHEADS*NSEQ*NSEQ];
static __device__ __half g_sil[(size_t)NBATCH*NSEQ*NSEQ*NHEADS];  // probs, head-interleaved
static __device__ __half g_xnh [MROWS*NDIM];
static __device__ __half g_rth [MROWS*NDIM];
static __device__ __half g_qkvh[MROWS*3*NHD];
static __device__ __half g_krh [MROWS*NHD];
static __device__ __half g_avh [MROWS*NHD];
static __device__ __half g_ffh [MROWS*NFF];
static __device__ __half g_wth [4*WT_TOTAL];
static __device__ __half g_vth [NBATCH*NHEADS*NDH*NSEQ];

// ---------------- primitives ------------------------------------------------
__device__ __forceinline__ uint32_t smem_u32(const void* p) {
    uint32_t a;
    asm("{ .reg .u64 t; cvta.to.shared.u64 t, %1; cvt.u32.u64 %0, t; }"
        : "=r"(a) : "l"(p));
    return a;
}
__device__ __forceinline__ void cp16(uint32_t dst, const void* src) {
    asm volatile("cp.async.cg.shared.global [%0], [%1], 16;" :: "r"(dst), "l"(src));
}
#define CP_COMMIT() asm volatile("cp.async.commit_group;")
#define CP_WAIT(n)  asm volatile("cp.async.wait_group %0;" :: "n"(n))

__device__ __forceinline__ void mma_f16(float* d, const uint32_t* a, const uint32_t* b) {
    asm volatile(
        "mma.sync.aligned.m16n8k16.row.col.f32.f16.f16.f32 "
        "{%0,%1,%2,%3}, {%4,%5,%6,%7}, {%8,%9}, {%0,%1,%2,%3};"
        : "+f"(d[0]), "+f"(d[1]), "+f"(d[2]), "+f"(d[3])
        : "r"(a[0]), "r"(a[1]), "r"(a[2]), "r"(a[3]), "r"(b[0]), "r"(b[1]));
}
__device__ __forceinline__ void ldm_x4(uint32_t* r, uint32_t addr) {
    asm volatile("ldmatrix.sync.aligned.m8n8.x4.shared.b16 {%0,%1,%2,%3}, [%4];"
        : "=r"(r[0]), "=r"(r[1]), "=r"(r[2]), "=r"(r[3]) : "r"(addr));
}
__device__ __forceinline__ void ldm_x2(uint32_t* r, uint32_t addr) {
    asm volatile("ldmatrix.sync.aligned.m8n8.x2.shared.b16 {%0,%1}, [%2];"
        : "=r"(r[0]), "=r"(r[1]) : "r"(addr));
}
__device__ __forceinline__ float gelu_exact(float v) {
    return 0.5f * v * (1.0f + erff(v * 0.70710678118654752f));
}

// ---------- merged weight transpose (hi-only) for ALL layers -----------------
__global__ __launch_bounds__(256) void transpose_all_kernel(
    const float* __restrict__ Wqkv, const float* __restrict__ Wkr,
    const float* __restrict__ Wout, const float* __restrict__ W1,
    const float* __restrict__ W2,
    __half* __restrict__ Wth)
{
    __shared__ float t[32][33];
    const int l = blockIdx.y;
    const int tt = blockIdx.x;
    const float* W; int K, N, off, tloc;
    if (tt < 768)       { W = Wqkv + (size_t)l * 786432;  K = 512;  N = 1536; off = WQKVT; tloc = tt; }
    else if (tt < 1024) { W = Wkr  + (size_t)l * 262144;  K = 512;  N = 512;  off = WKRT;  tloc = tt - 768; }
    else if (tt < 1280) { W = Wout + (size_t)l * 262144;  K = 512;  N = 512;  off = WOUTT; tloc = tt - 1024; }
    else if (tt < 2304) { W = W1   + (size_t)l * 1048576; K = 512;  N = 2048; off = W1T;   tloc = tt - 1280; }
    else                { W = W2   + (size_t)l * 1048576; K = 2048; N = 512;  off = W2T;   tloc = tt - 2304; }
    const int ntn = N >> 5;
    const int kt = tloc / ntn, nt = tloc % ntn;
    const int k0 = kt * 32, n0 = nt * 32;
    const int x = threadIdx.x, y = threadIdx.y;
    const size_t dst = (size_t)l * WT_TOTAL + off;
#pragma unroll
    for (int i = 0; i < 32; i += 8)
        t[y + i][x] = W[(size_t)(k0 + y + i) * N + n0 + x];
    __syncthreads();
#pragma unroll
    for (int i = 0; i < 32; i += 8)
        Wth[dst + (size_t)(n0 + y + i) * K + k0 + x] = __float2half_rn(t[x][y + i]);
}

// ---------------- r_t -> fp16 ----------------------------------------
__global__ __launch_bounds__(256) void split_rt_kernel(
    const float* __restrict__ src, __half* __restrict__ dh)
{
    const size_t i = ((size_t)blockIdx.x * 256 + threadIdx.x) * 4;
    float4 v = *(const float4*)(src + i);
    __half2 a, b;
    a.x = __float2half_rn(v.x); a.y = __float2half_rn(v.y);
    b.x = __float2half_rn(v.z); b.y = __float2half_rn(v.w);
    *(__half2*)(dh + i) = a;
    *(__half2*)(dh + i + 2) = b;
}

// ---------------- LayerNorm -> fp16 ------------------------------------------
__global__ __launch_bounds__(128) void ln_half_kernel(
    const float* __restrict__ x, const float* __restrict__ g,
    const float* __restrict__ b, __half* __restrict__ yh)
{
    const int row = blockIdx.x;
    const int tid = threadIdx.x;
    const float* xr = x + (size_t)row * NDIM;

    float4 v = ((const float4*)xr)[tid];
    float s  = v.x + v.y + v.z + v.w;
    float sq = v.x*v.x + v.y*v.y + v.z*v.z + v.w*v.w;
#pragma unroll
    for (int o = 16; o > 0; o >>= 1) {
        s  += __shfl_xor_sync(0xffffffffu, s,  o);
        sq += __shfl_xor_sync(0xffffffffu, sq, o);
    }
    __shared__ float red[8];
    const int w = tid >> 5;
    if ((tid & 31) == 0) { red[w] = s; red[4 + w] = sq; }
    __syncthreads();
    const float st  = red[0] + red[1] + red[2] + red[3];
    const float sqt = red[4] + red[5] + red[6] + red[7];
    const float mu  = st * (1.0f / NDIM);
    const float var = sqt * (1.0f / NDIM) - mu * mu;
    const float inv = rsqrtf(var + 1e-5f);

    float4 gg = ((const float4*)g)[tid];
    float4 bb = ((const float4*)b)[tid];
    __half2 a, c;
    a.x = __float2half_rn((v.x - mu) * inv * gg.x + bb.x);
    a.y = __float2half_rn((v.y - mu) * inv * gg.y + bb.y);
    c.x = __float2half_rn((v.z - mu) * inv * gg.z + bb.z);
    c.y = __float2half_rn((v.w - mu) * inv * gg.w + bb.w);
    const size_t base = (size_t)row * NDIM + tid * 4;
    *(__half2*)(yh + base) = a;
    *(__half2*)(yh + base + 2) = c;
}

// ====== dense fp16 mma GEMM, 3-stage cp.async pipeline, 1-term ===============
#define LDS 40
#define ARR   (128*LDS)
#define ARRB  (ARR*2)
#define MMA_SMEM1 (3*2*ARRB)   // 61440

template<int SPLIT, int ACT>
__global__ __launch_bounds__(256, 2) void mma1_kernel(
    const __half* __restrict__ Ah, const __half* __restrict__ Bh,
    float* __restrict__ Cf, __half* __restrict__ Ch,
    const float* __restrict__ bias, const float* __restrict__ res,
    int M, int N, int K)
{
    constexpr uint32_t STAGEB = 2u * ARRB;
    extern __shared__ char dsm[];
    const uint32_t sbase = smem_u32(dsm);
    const int tid = threadIdx.x, wid = tid >> 5, lane = tid & 31;
    const int wm = wid >> 2, wn = wid & 3;
    const int bm = blockIdx.y * 128, bn = blockIdx.x * 128;

    const int lrow = tid >> 2, lcc = (tid & 3) * 8;
    const int lrow2 = (tid + 256) >> 2, lcc2 = ((tid + 256) & 3) * 8;

#define MMA1_ISSUE(kt, s) do {                                                   \
        const uint32_t st_ = sbase + (uint32_t)(s) * STAGEB;                     \
        const int k0_ = (kt) * 32;                                               \
        cp16(st_ + (uint32_t)((lrow * LDS + lcc) * 2),                           \
             Ah + (size_t)(bm + lrow) * K + k0_ + lcc);                          \
        cp16(st_ + (uint32_t)((lrow2 * LDS + lcc2) * 2),                         \
             Ah + (size_t)(bm + lrow2) * K + k0_ + lcc2);                        \
        cp16(st_ + (uint32_t)ARRB + (uint32_t)((lrow * LDS + lcc) * 2),          \
             Bh + (size_t)(bn + lrow) * K + k0_ + lcc);                          \
        cp16(st_ + (uint32_t)ARRB + (uint32_t)((lrow2 * LDS + lcc2) * 2),        \
             Bh + (size_t)(bn + lrow2) * K + k0_ + lcc2);                        \
    } while (0)

    const int l15 = lane & 15;
    const uint32_t aoff = (uint32_t)(((wm * 64 + l15) * LDS + ((lane >> 4) << 3)) * 2);
    const uint32_t boff = (uint32_t)(((wn * 32 + (l15 & 7)) * LDS + (((l15 >> 3) & 1) << 3)) * 2);

    float acc[4][4][4];
#pragma unroll
    for (int i = 0; i < 4; ++i)
#pragma unroll
        for (int j = 0; j < 4; ++j)
#pragma unroll
            for (int q = 0; q < 4; ++q) acc[i][j][q] = 0.0f;

    const int NKT = K >> 5;
    MMA1_ISSUE(0, 0);
    CP_COMMIT();
    MMA1_ISSUE(1, 1);
    CP_COMMIT();

    for (int kt = 0; kt < NKT; ++kt) {
        if (kt + 1 < NKT) { CP_WAIT(1); } else { CP_WAIT(0); }
        __syncthreads();
        if (kt + 2 < NKT) {
            MMA1_ISSUE(kt + 2, (kt + 2) % 3);
            CP_COMMIT();
        }
        const uint32_t st = sbase + (uint32_t)(kt % 3) * STAGEB;
        const uint32_t aAh = st, aBh = st + ARRB;
#pragma unroll
        for (int kk = 0; kk < 32; kk += 16) {
            uint32_t bh[4][2], a[4][4];
#pragma unroll
            for (int nt = 0; nt < 4; ++nt)
                ldm_x2(bh[nt], aBh + boff + (uint32_t)((nt * 8 * LDS + kk) * 2));
#pragma unroll
            for (int mt = 0; mt < 4; ++mt)
                ldm_x4(a[mt], aAh + aoff + (uint32_t)((mt * 16 * LDS + kk) * 2));
#pragma unroll
            for (int mt = 0; mt < 4; ++mt)
#pragma unroll
                for (int nt = 0; nt < 4; ++nt)
                    mma_f16(acc[mt][nt], a[mt], bh[nt]);
        }
    }
#undef MMA1_ISSUE
    __syncthreads();

    const int g = lane >> 2, t2 = (lane & 3) * 2;
#pragma unroll
    for (int mt = 0; mt < 4; ++mt) {
#pragma unroll
        for (int nt = 0; nt < 4; ++nt) {
            const int r0 = bm + wm * 64 + mt * 16 + g;
            const int r1 = r0 + 8;
            const int c  = bn + wn * 32 + nt * 8 + t2;
            float v0 = acc[mt][nt][0], v1 = acc[mt][nt][1];
            float v2 = acc[mt][nt][2], v3 = acc[mt][nt][3];
            if (bias) {
                const float b0 = bias[c], b1 = bias[c + 1];
                v0 += b0; v1 += b1; v2 += b0; v3 += b1;
            }
            if (ACT) {
                v0 = gelu_exact(v0); v1 = gelu_exact(v1);
                v2 = gelu_exact(v2); v3 = gelu_exact(v3);
            }
            if (SPLIT == 2) {
                __half2 hp;
                hp.x = __float2half_rn(v0); hp.y = __float2half_rn(v1);
                *(__half2*)(Ch + (size_t)r0 * N + c) = hp;
                hp.x = __float2half_rn(v2); hp.y = __float2half_rn(v3);
                *(__half2*)(Ch + (size_t)r1 * N + c) = hp;
            } else {
                if (res) {
                    const float2 q0 = *(const float2*)(res + (size_t)r0 * N + c);
                    const float2 q1 = *(const float2*)(res + (size_t)r1 * N + c);
                    v0 += q0.x; v1 += q0.y; v2 += q1.x; v3 += q1.y;
                }
                *(float2*)(Cf + (size_t)r0 * N + c) = make_float2(v0, v1);
                *(float2*)(Cf + (size_t)r1 * N + c) = make_float2(v2, v3);
            }
        }
    }
}

// ---------------- bias rank-1 terms (hi-only inputs) -------------------------
__global__ __launch_bounds__(256) void bias_terms_kernel(
    const __half* __restrict__ qkvh, const __half* __restrict__ krh,
    const float* __restrict__ bias_pf,
    float* __restrict__ bk, float* __restrict__ br)
{
    const int idx = blockIdx.x * 256 + threadIdx.x;
    const int bh = idx >> 10, j = idx & 1023;
    const int b = bh >> 3, h = bh & 7;
    const size_t kb = ((size_t)b * NSEQ + j) * 1536 + 512 + h * 64;
    const size_t rb = ((size_t)b * NSEQ + j) * 512 + h * 64;
    float sk = 0.0f, sr = 0.0f;
#pragma unroll 16
    for (int d = 0; d < 64; ++d) {
        const float bp = bias_pf[h * 64 + d];
        sk += bp * __half2float(qkvh[kb + d]);
        sr += bp * __half2float(krh[rb + d]);
    }
    bk[idx] = sk;
    br[idx] = sr;
}

// =========== acbd fp16 mma, 1-term; fp16 score output ========================
#define ACBD_STAGE (2*ARR)
#define ACBD_SMEM  (2*ACBD_STAGE*2)   // 40960 bytes

__global__ __launch_bounds__(256, 2) void acbd1_kernel(
    const __half* __restrict__ qkvh, const __half* __restrict__ krh,
    const float* __restrict__ bk, const float* __restrict__ br,
    __half* __restrict__ AC, __half* __restrict__ BD)
{
    extern __shared__ char dsm[];
    const uint32_t sbase = smem_u32(dsm);
    const int tid = threadIdx.x, wid = tid >> 5, lane = tid & 31;
    const int wm = wid >> 2, wn = wid & 3;
    const int z = blockIdx.z, bh_idx = z & 63, isBD = z >> 6;
    const int b = bh_idx >> 3, h = bh_idx & 7;
    const int i0 = blockIdx.y * 128, j0 = blockIdx.x * 128;

    const __half* Ah = qkvh + ((size_t)b * NSEQ + i0) * 1536 + h * 64;
    const __half* Bh = isBD ? (krh + ((size_t)b * NSEQ + j0) * 512 + h * 64)
                            : (qkvh + ((size_t)b * NSEQ + j0) * 1536 + 512 + h * 64);
    const int ldb = isBD ? 512 : 1536;
    __half* Cbase = (isBD ? BD : AC) + (size_t)bh_idx * NSEQ * NSEQ;
    const float* bvec = (isBD ? br : bk) + (size_t)bh_idx * NSEQ;

    const int lrow = tid >> 2, lcc = (tid & 3) * 8;
    const int lrow2 = (tid + 256) >> 2, lcc2 = ((tid + 256) & 3) * 8;

#define ACBD_ISSUE(kt, s) do {                                                   \
        const uint32_t st_ = sbase + (uint32_t)(s) * (ACBD_STAGE * 2);           \
        const int k0_ = (kt) * 32;                                               \
        cp16(st_ + (uint32_t)((lrow * LDS + lcc) * 2),                           \
             Ah + (size_t)lrow * 1536 + k0_ + lcc);                              \
        cp16(st_ + (uint32_t)((lrow2 * LDS + lcc2) * 2),                         \
             Ah + (size_t)lrow2 * 1536 + k0_ + lcc2);                            \
        cp16(st_ + (uint32_t)(ARR * 2) + (uint32_t)((lrow * LDS + lcc) * 2),     \
             Bh + (size_t)lrow * ldb + k0_ + lcc);                               \
        cp16(st_ + (uint32_t)(ARR * 2) + (uint32_t)((lrow2 * LDS + lcc2) * 2),   \
             Bh + (size_t)lrow2 * ldb + k0_ + lcc2);                             \
    } while (0)

    const int l15 = lane & 15;
    const uint32_t aoff = (uint32_t)(((wm * 64 + l15) * LDS + ((lane >> 4) << 3)) * 2);
    const uint32_t boff = (uint32_t)(((wn * 32 + (l15 & 7)) * LDS + (((l15 >> 3) & 1) << 3)) * 2);

    float acc[4][4][4];
#pragma unroll
    for (int i = 0; i < 4; ++i)
#pragma unroll
        for (int j = 0; j < 4; ++j)
#pragma unroll
            for (int q = 0; q < 4; ++q) acc[i][j][q] = 0.0f;

    ACBD_ISSUE(0, 0);
    CP_COMMIT();
#pragma unroll
    for (int kt = 0; kt < 2; ++kt) {
        if (kt == 0) {
            ACBD_ISSUE(1, 1);
            CP_COMMIT();
            CP_WAIT(1);
        } else {
            CP_WAIT(0);
        }
        __syncthreads();
        const uint32_t st = sbase + (uint32_t)(kt & 1) * (ACBD_STAGE * 2);
        const uint32_t aAh = st, aBh = st + ARR * 2;
#pragma unroll
        for (int kk = 0; kk < 32; kk += 16) {
            uint32_t bh[4][2], a[4][4];
#pragma unroll
            for (int nt = 0; nt < 4; ++nt)
                ldm_x2(bh[nt], aBh + boff + (uint32_t)((nt * 8 * LDS + kk) * 2));
#pragma unroll
            for (int mt = 0; mt < 4; ++mt)
                ldm_x4(a[mt], aAh + aoff + (uint32_t)((mt * 16 * LDS + kk) * 2));
#pragma unroll
            for (int mt = 0; mt < 4; ++mt)
#pragma unroll
                for (int nt = 0; nt < 4; ++nt)
                    mma_f16(acc[mt][nt], a[mt], bh[nt]);
        }
        __syncthreads();
    }
#undef ACBD_ISSUE

    const int g = lane >> 2, t2 = (lane & 3) * 2;
#pragma unroll
    for (int mt = 0; mt < 4; ++mt) {
#pragma unroll
        for (int nt = 0; nt < 4; ++nt) {
            const int r0 = i0 + wm * 64 + mt * 16 + g;
            const int c  = j0 + wn * 32 + nt * 8 + t2;
            const float b0 = bvec[c], b1 = bvec[c + 1];
            __half2 p;
            p.x = __float2half_rn(acc[mt][nt][0] + b0);
            p.y = __float2half_rn(acc[mt][nt][1] + b1);
            *(__half2*)(Cbase + (size_t)r0 * NSEQ + c) = p;
            p.x = __float2half_rn(acc[mt][nt][2] + b0);
            p.y = __float2half_rn(acc[mt][nt][3] + b1);
            *(__half2*)(Cbase + (size_t)(r0 + 8) * NSEQ + c) = p;
        }
    }
}

// ---------------- V transpose (hi only) --------------------------------------
__global__ __launch_bounds__(256) void vt_kernel(
    const __half* __restrict__ qkvh, __half* __restrict__ vth)
{
    __shared__ __half th[32][33];
    const int bh = blockIdx.z, b = bh >> 3, h = bh & 7;
    const int j0 = blockIdx.x * 32, d0 = blockIdx.y * 32;
    const int x = threadIdx.x, y = threadIdx.y;
#pragma unroll
    for (int i = 0; i < 32; i += 8)
        th[y + i][x] = qkvh[((size_t)b * NSEQ + j0 + y + i) * 1536 + 1024 + h * 64 + d0 + x];
    __syncthreads();
#pragma unroll
    for (int i = 0; i < 32; i += 8)
        vth[((size_t)bh * 64 + d0 + y + i) * NSEQ + j0 + x] = th[x][y + i];
}

// ======= rel_shift + scale + softmax(heads) -> head-interleaved probs ========
// Output S[b][i][j][h], 8 halves contiguous per (i,j). High-occupancy grid.
__global__ __launch_bounds__(256) void softmax_il_kernel(
    const __half* __restrict__ AC, const __half* __restrict__ BDp,
    __half* __restrict__ S, float* __restrict__ attnf)
{
    const int jp = blockIdx.x * 256 + threadIdx.x;   // 0..511 (grid.x = 2)
    const int i  = blockIdx.y;
    const int b  = blockIdx.z;
    const int bq = b * NHEADS;

    float p0[8], p1[8];
#pragma unroll
    for (int e = 0; e < 2; ++e) {
        const int gj = jp * 2 + e;
        const int g = (i + 1) * NSEQ + gj;
        const int si = g / (NSEQ + 1);
        const int sj = g % (NSEQ + 1) - 1;
        float v[8];
        float mx = -1e30f;
#pragma unroll
        for (int hh = 0; hh < 8; ++hh) {
            const size_t base = (size_t)(bq + hh) * NSEQ;
            float d = __half2float(AC[(base + i) * NSEQ + gj]);
            if (sj >= 0) d += __half2float(BDp[(base + si) * NSEQ + sj]);
            d *= 0.125f;
            v[hh] = d;
            mx = fmaxf(mx, d);
        }
        float s = 0.0f;
#pragma unroll
        for (int hh = 0; hh < 8; ++hh) { v[hh] = __expf(v[hh] - mx); s += v[hh]; }
        const float inv = 1.0f / s;
        float* pp = e ? p1 : p0;
#pragma unroll
        for (int hh = 0; hh < 8; ++hh) pp[hh] = v[hh] * inv;
    }

    union { uint4 u[2]; __half h[16]; } o;
#pragma unroll
    for (int hh = 0; hh < 8; ++hh) {
        o.h[hh]     = __float2half_rn(p0[hh]);
        o.h[8 + hh] = __float2half_rn(p1[hh]);
    }
    const size_t off = (((size_t)b * NSEQ + i) * NSEQ + (size_t)jp * 2) * 8;
    *(uint4*)(S + off)     = o.u[0];
    *(uint4*)(S + off + 8) = o.u[1];

    if (attnf) {
#pragma unroll
        for (int hh = 0; hh < 8; ++hh)
            *(float2*)(attnf + ((size_t)(bq + hh) * NSEQ + i) * NSEQ + jp * 2) =
                make_float2(p0[hh], p1[hh]);
    }
}

// ======= attn@V: probs staged from interleaved S, double-buffered ============
#define SAV_ATT(buf) ((uint32_t)(buf) * 40960u)
#define SAV_V(buf)   (81920u + (uint32_t)(buf) * 40960u)
#define SAV_SMEM  163840

__global__ __launch_bounds__(512, 1) void av_il_kernel(
    const __half* __restrict__ S, const __half* __restrict__ vth,
    __half* __restrict__ outh)
{
    extern __shared__ char dsm[];
    const uint32_t sb = smem_u32(dsm);
    const int tid = threadIdx.x, wid = tid >> 5, lane = tid & 31;
    const int b = blockIdx.y;
    const int i0 = blockIdx.x * 64;
    const int bq = b * NHEADS;

    const int ibA = tid >> 4;
    const int jjA = (tid & 15) * 2;

    const int h = wid & 7, ihalf = wid >> 3;
    const int l15 = lane & 15;
    const uint32_t headOff = (uint32_t)(h * 64 * 40 * 2);
    const uint32_t aoff = (uint32_t)(((ihalf * 32 + l15) * 40 + ((lane >> 4) << 3)) * 2);
    const uint32_t boff = (uint32_t)(((l15 & 7) * 40 + (((l15 >> 3) & 1) << 3)) * 2);

    const __half* Sb = S + ((size_t)b * NSEQ + i0) * NSEQ * 8;

    float acc[2][8][4];
#pragma unroll
    for (int i = 0; i < 2; ++i)
#pragma unroll
        for (int j = 0; j < 8; ++j)
#pragma unroll
            for (int q = 0; q < 4; ++q) acc[i][j][q] = 0.0f;

#define AV_VISSUE(ktv, buf) do {                                                 \
        const int j0_ = (ktv) * 32;                                              \
        _Pragma("unroll")                                                        \
        for (int k_ = 0; k_ < 4; ++k_) {                                         \
            const int idx_ = tid + k_ * 512;                                     \
            const int hv_ = idx_ >> 8;                                           \
            const int r_ = idx_ & 255;                                           \
            const int d_ = r_ >> 2, seg_ = r_ & 3;                               \
            const uint32_t so_ = (uint32_t)((hv_ * 64 + d_) * 80 + seg_ * 16);   \
            const size_t gsrc_ = (((size_t)(bq + hv_) * 64 + d_) << 10) + j0_ + seg_ * 8; \
            cp16(sb + SAV_V(buf) + so_, vth + gsrc_);                            \
        }                                                                        \
        CP_COMMIT();                                                             \
    } while (0)

    // stage probs(ktv) from interleaved S into per-head att buffer `buf`
#define AV_STAGE(ktv, buf) do {                                                  \
        const int j0_ = (ktv) * 32;                                              \
        _Pragma("unroll")                                                        \
        for (int it_ = 0; it_ < 2; ++it_) {                                      \
            const int i_ = ibA + it_ * 32;                                       \
            const uint4* pa_ = (const uint4*)(Sb + ((size_t)i_ * NSEQ + j0_ + jjA) * 8); \
            union { uint4 u; __half h[8]; } A_, B_;                              \
            A_.u = pa_[0];                                                       \
            B_.u = pa_[1];                                                       \
            _Pragma("unroll")                                                    \
            for (int hh_ = 0; hh_ < 8; ++hh_) {                                  \
                __half2 hp_;                                                     \
                hp_.x = A_.h[hh_];                                               \
                hp_.y = B_.h[hh_];                                               \
                const uint32_t so_ = (uint32_t)(((hh_ * 64 + i_) * 40 + jjA) * 2);\
                *(__half2*)(dsm + SAV_ATT(buf) + so_) = hp_;                     \
            }                                                                    \
        }                                                                        \
    } while (0)

    AV_VISSUE(0, 0);
    AV_STAGE(0, 0);

    for (int kt = 0; kt < 32; ++kt) {
        const int buf = kt & 1;
        CP_WAIT(0);
        __syncthreads();
        if (kt + 1 < 32)
            AV_VISSUE(kt + 1, buf ^ 1);

        const uint32_t aAH = sb + SAV_ATT(buf) + headOff;
        const uint32_t aVH = sb + SAV_V(buf) + headOff;
#pragma unroll
        for (int kk = 0; kk < 32; kk += 16) {
            uint32_t bhf[8][2], ah[2][4];
#pragma unroll
            for (int nt = 0; nt < 8; ++nt)
                ldm_x2(bhf[nt], aVH + boff + (uint32_t)((nt * 8 * 40 + kk) * 2));
#pragma unroll
            for (int mt = 0; mt < 2; ++mt)
                ldm_x4(ah[mt], aAH + aoff + (uint32_t)((mt * 16 * 40 + kk) * 2));
#pragma unroll
            for (int mt = 0; mt < 2; ++mt)
#pragma unroll
                for (int nt = 0; nt < 8; ++nt)
                    mma_f16(acc[mt][nt], ah[mt], bhf[nt]);
        }

        if (kt + 1 < 32)
            AV_STAGE(kt + 1, buf ^ 1);
    }
#undef AV_VISSUE
#undef AV_STAGE

    const int g = lane >> 2, t2 = (lane & 3) * 2;
#pragma unroll
    for (int mt = 0; mt < 2; ++mt) {
#pragma unroll
        for (int nt = 0; nt < 8; ++nt) {
            const int r0 = i0 + ihalf * 32 + mt * 16 + g;
            const int c  = h * 64 + nt * 8 + t2;
            __half2 hp;
            hp.x = __float2half_rn(acc[mt][nt][0]);
            hp.y = __float2half_rn(acc[mt][nt][1]);
            *(__half2*)(outh + ((size_t)b * NSEQ + r0) * NHD + c) = hp;
            hp.x = __float2half_rn(acc[mt][nt][2]);
            hp.y = __float2half_rn(acc[mt][nt][3]);
            *(__half2*)(outh + ((size_t)b * NSEQ + r0 + 8) * NHD + c) = hp;
        }
    }
}

// ---------------- host orchestration ----------------------------------------
extern "C" void kernel_launch(void* const* d_in, const int* in_sizes, int n_in,
                              void* d_out, int out_size)
{
    (void)in_sizes; (void)n_in;
    const float* x_in    = (const float*)d_in[0];
    const float* r_t     = (const float*)d_in[1];
    const float* bias_pf = (const float*)d_in[3];
    const float* ln1_g   = (const float*)d_in[4];
    const float* ln1_b   = (const float*)d_in[5];
    const float* Wqkv    = (const float*)d_in[6];
    const float* Wkr_t   = (const float*)d_in[7];
    const float* Wout    = (const float*)d_in[9];
    const float* bout    = (const float*)d_in[10];
    const float* ln2_g   = (const float*)d_in[11];
    const float* ln2_b   = (const float*)d_in[12];
    const float* W1      = (const float*)d_in[13];
    const float* b1      = (const float*)d_in[14];
    const float* W2      = (const float*)d_in[15];
    const float* b2      = (const float*)d_in[16];
    float* outp = (float*)d_out;

    static int attr_done = 0;
    if (!attr_done) {
        cudaFuncSetAttribute(mma1_kernel<2,0>, cudaFuncAttributeMaxDynamicSharedMemorySize, MMA_SMEM1);
        cudaFuncSetAttribute(mma1_kernel<0,0>, cudaFuncAttributeMaxDynamicSharedMemorySize, MMA_SMEM1);
        cudaFuncSetAttribute(mma1_kernel<2,1>, cudaFuncAttributeMaxDynamicSharedMemorySize, MMA_SMEM1);
        cudaFuncSetAttribute(acbd1_kernel,     cudaFuncAttributeMaxDynamicSharedMemorySize, ACBD_SMEM);
        cudaFuncSetAttribute(av_il_kernel,     cudaFuncAttributeMaxDynamicSharedMemorySize, SAV_SMEM);
        attr_done = 1;
    }

    float *gx, *gbk, *gbr;
    __half *gac, *gbd, *gsil;
    __half *gxnh, *grth, *gqkvh, *gkrh, *gavh, *gffh, *gwth, *gvth;
    cudaGetSymbolAddress((void**)&gx,    g_x);
    cudaGetSymbolAddress((void**)&gac,   g_ac);
    cudaGetSymbolAddress((void**)&gbd,   g_bd);
    cudaGetSymbolAddress((void**)&gsil,  g_sil);
    cudaGetSymbolAddress((void**)&gbk,   g_bk);
    cudaGetSymbolAddress((void**)&gbr,   g_br);
    cudaGetSymbolAddress((void**)&gxnh,  g_xnh);
    cudaGetSymbolAddress((void**)&grth,  g_rth);
    cudaGetSymbolAddress((void**)&gqkvh, g_qkvh);
    cudaGetSymbolAddress((void**)&gkrh,  g_krh);
    cudaGetSymbolAddress((void**)&gavh,  g_avh);
    cudaGetSymbolAddress((void**)&gffh,  g_ffh);
    cudaGetSymbolAddress((void**)&gwth,  g_wth);
    cudaGetSymbolAddress((void**)&gvth,  g_vth);

    float* attn_out = outp + ((size_t)out_size - ATT_ELEMS);

    cudaMemcpyAsync(gx, x_in, X_ELEMS * sizeof(float), cudaMemcpyDeviceToDevice, 0);
    split_rt_kernel<<<X_ELEMS / 1024, 256>>>(r_t, grth);

    transpose_all_kernel<<<dim3(3328, 4), dim3(32, 8)>>>(
        Wqkv, Wkr_t, Wout, W1, W2, gwth);

    const dim3 tb(32, 8);
    for (int l = 0; l < 4; ++l) {
        const size_t wb = (size_t)l * WT_TOTAL;

        ln_half_kernel<<<MROWS, 128>>>(gx, ln1_g + l * NDIM, ln1_b + l * NDIM, gxnh);
        mma1_kernel<2,0><<<dim3(12, 64), 256, MMA_SMEM1>>>(
            gxnh, gwth + wb + WQKVT, nullptr, gqkvh, nullptr, nullptr, MROWS, 1536, 512);
        mma1_kernel<2,0><<<dim3(4, 64), 256, MMA_SMEM1>>>(
            grth, gwth + wb + WKRT, nullptr, gkrh, nullptr, nullptr, MROWS, 512, 512);

        bias_terms_kernel<<<256, 256>>>(gqkvh, gkrh, bias_pf, gbk, gbr);

        acbd1_kernel<<<dim3(8, 8, 128), 256, ACBD_SMEM>>>(
            gqkvh, gkrh, gbk, gbr, gac, gbd);

        vt_kernel<<<dim3(32, 2, 64), tb>>>(gqkvh, gvth);

        // softmax (high occupancy) -> head-interleaved probs
        softmax_il_kernel<<<dim3(2, NSEQ, NBATCH), 256>>>(
            gac, gbd, gsil, (l == 3) ? attn_out : nullptr);

        // attn @ V from interleaved probs
        av_il_kernel<<<dim3(16, 8), 512, SAV_SMEM>>>(gsil, gvth, gavh);

        mma1_kernel<0,0><<<dim3(4, 64), 256, MMA_SMEM1>>>(
            gavh, gwth + wb + WOUTT, gx, nullptr, bout + l * NDIM, gx, MROWS, 512, 512);

        ln_half_kernel<<<MROWS, 128>>>(gx, ln2_g + l * NDIM, ln2_b + l * NDIM, gxnh);
        mma1_kernel<2,1><<<dim3(16, 64), 256, MMA_SMEM1>>>(
            gxnh, gwth + wb + W1T, nullptr, gffh, b1 + l * NFF, nullptr, MROWS, 2048, 512);
        float* xdst = (l == 3) ? outp : gx;
        mma1_kernel<0,0><<<dim3(4, 64), 256, MMA_SMEM1>>>(
            gffh, gwth + wb + W2T, xdst, nullptr, b2 + l * NDIM, gx, MROWS, 512, 2048);
    }
}